// round 16
// baseline (speedup 1.0000x reference)
#include <cuda_runtime.h>
#include <math_constants.h>

// kNN graph, PyG knn_graph(loop=False): B=16 graphs x n=4096 pts, D=3, k=16.
// R15 engine with a 3-instruction push (setp; @p st; @p add on the absolute
// FIFO address) replacing the 5-instruction selp form.
// Output (float32 flat): [nbr_global | centers | topk_d2], each total_n*K,
// ordering (b*n+i)*K + m (matches reference reshape(-1)).

#define K        16
#define KP1      17            // keep k+1; self entry removed at output
#define NPER     4096
#define TPB      256
#define CPG      (NPER / TPB)  // 16 CTAs per graph
#define PB       20            // u32 FIFO slots: cnt<=4 entering body, +16 = 20
#define SLOT_B   (TPB * 4u)    // 1024 B between a thread's slots
#define FLUSH_B  (5u * SLOT_B) // flush when cnt >= 5

// smem byte offsets
#define SM_SX    0
#define SM_SY    16384
#define SM_SZ    32768
#define SM_SS    49152
#define SM_PEND  65536                  // u32[PB][256] = 20480
#define SM_TOTAL (65536 + 20480)        // 86016 -> 2 CTAs/SM

#define FMA_F32X2(out, a, b, c) \
    asm("fma.rn.f32x2 %0, %1, %2, %3;" : "=l"(out) : "l"(a), "l"(b), "l"(c))
#define MUL_F32X2_(out, a, b) \
    asm("mul.rn.f32x2 %0, %1, %2;" : "=l"(out) : "l"(a), "l"(b))
#define ADD_F32X2_(out, a, b) \
    asm("add.rn.f32x2 %0, %1, %2;" : "=l"(out) : "l"(a), "l"(b))
#define PACK2(out, lo, hi) \
    asm("mov.b64 %0, {%1, %2};" : "=l"(out) : "r"(lo), "r"(hi))
#define UNPACK2(lo, hi, in) \
    asm("mov.b64 {%0, %1}, %2;" : "=r"(lo), "=r"(hi) : "l"(in))

// 3-instruction branchless push: one setp guards BOTH the u32 store to the
// absolute FIFO address and the address bump. No BSSY/BSYNC, no separate
// address IADD, no selp.
#define PUSH32(dv, jv)                                                        \
    asm volatile(                                                             \
        "{\n\t.reg .pred p;\n\t"                                              \
        "setp.le.f32 p, %1, %2;\n\t"                                          \
        "@p st.shared.b32 [%0], %3;\n\t"                                      \
        "@p add.u32 %0, %0, %4;\n\t}"                                         \
        : "+r"(aaddr)                                                         \
        : "f"(dv), "f"(worst), "r"((unsigned)(jv)), "n"(SLOT_B)               \
        : "memory")

// Drain this lane's FIFO (indices only; distance recomputed with the exact
// same fma sequence -> identical bits). Per-lane divergent guard + strict '<'
// sorted-insert chain: FIFO arrival order is ascending j, so equal distances
// keep the earlier/lower index — jax.lax.top_k semantics (R6/R15-validated).
#define DRAIN()                                                               \
    {                                                                         \
        const int cnt_ = (int)((aaddr - abase) >> 10);                        \
        aaddr = abase;                                                        \
        const unsigned* myp_ = pend + tid;                                    \
        _Pragma("unroll 1")                                                   \
        for (int p_ = 0; p_ < cnt_; ++p_) {                                   \
            const int jc_ = (int)myp_[(size_t)p_ * TPB];                      \
            const float dot_ =                                                \
                fmaf(qz, sz[jc_], fmaf(qy, sy[jc_], qx * sx[jc_]));           \
            float dc_ = fmaf(-2.f, dot_, qs + ss[jc_]);                       \
            int   ic_ = jc_;                                                  \
            if (dc_ < worst) {                                                \
                _Pragma("unroll")                                             \
                for (int m_ = 0; m_ < KP1; ++m_) {                            \
                    const bool  sw_ = dc_ < bd[m_];                           \
                    const float fo_ = sw_ ? bd[m_] : dc_;                     \
                    const int   io_ = sw_ ? bi[m_] : ic_;                     \
                    bd[m_] = sw_ ? dc_ : bd[m_];                              \
                    bi[m_] = sw_ ? ic_ : bi[m_];                              \
                    dc_ = fo_; ic_ = io_;                                     \
                }                                                             \
                worst = bd[KP1 - 1];                                          \
            }                                                                 \
        }                                                                     \
    }

// 8 candidates: LDS.128 broadcasts, f32x2 distance (exact reference op
// order/rounding), 8 branchless pushes. Macro-local index is jb_ (NOT j0):
// naming it j0 and invoking BLOCK8(j0+8) self-shadows (the R14 crash).
#define BLOCK8(j0_)                                                           \
    {                                                                         \
        const int jb_ = (j0_);                                                \
        const ulonglong2 Xa = *(const ulonglong2*)(sx + jb_);                 \
        const ulonglong2 Ya = *(const ulonglong2*)(sy + jb_);                 \
        const ulonglong2 Za = *(const ulonglong2*)(sz + jb_);                 \
        const ulonglong2 Sa = *(const ulonglong2*)(ss + jb_);                 \
        const ulonglong2 Xb = *(const ulonglong2*)(sx + jb_ + 4);             \
        const ulonglong2 Yb = *(const ulonglong2*)(sy + jb_ + 4);             \
        const ulonglong2 Zb = *(const ulonglong2*)(sz + jb_ + 4);             \
        const ulonglong2 Sb = *(const ulonglong2*)(ss + jb_ + 4);             \
        unsigned long long dt, tt, dp0, dp1, dp2, dp3;                        \
        MUL_F32X2_(dt, qx2, Xa.x); FMA_F32X2(dt, qy2, Ya.x, dt);              \
        FMA_F32X2(dt, qz2, Za.x, dt);                                         \
        ADD_F32X2_(tt, Sa.x, qs2); FMA_F32X2(dp0, m2, dt, tt);                \
        MUL_F32X2_(dt, qx2, Xa.y); FMA_F32X2(dt, qy2, Ya.y, dt);              \
        FMA_F32X2(dt, qz2, Za.y, dt);                                         \
        ADD_F32X2_(tt, Sa.y, qs2); FMA_F32X2(dp1, m2, dt, tt);                \
        MUL_F32X2_(dt, qx2, Xb.x); FMA_F32X2(dt, qy2, Yb.x, dt);              \
        FMA_F32X2(dt, qz2, Zb.x, dt);                                         \
        ADD_F32X2_(tt, Sb.x, qs2); FMA_F32X2(dp2, m2, dt, tt);                \
        MUL_F32X2_(dt, qx2, Xb.y); FMA_F32X2(dt, qy2, Yb.y, dt);              \
        FMA_F32X2(dt, qz2, Zb.y, dt);                                         \
        ADD_F32X2_(tt, Sb.y, qs2); FMA_F32X2(dp3, m2, dt, tt);                \
        unsigned u0, u1, u2, u3, u4, u5, u6, u7;                              \
        UNPACK2(u0, u1, dp0); UNPACK2(u2, u3, dp1);                           \
        UNPACK2(u4, u5, dp2); UNPACK2(u6, u7, dp3);                           \
        PUSH32(__uint_as_float(u0), jb_ + 0);                                 \
        PUSH32(__uint_as_float(u1), jb_ + 1);                                 \
        PUSH32(__uint_as_float(u2), jb_ + 2);                                 \
        PUSH32(__uint_as_float(u3), jb_ + 3);                                 \
        PUSH32(__uint_as_float(u4), jb_ + 4);                                 \
        PUSH32(__uint_as_float(u5), jb_ + 5);                                 \
        PUSH32(__uint_as_float(u6), jb_ + 6);                                 \
        PUSH32(__uint_as_float(u7), jb_ + 7);                                 \
    }

__global__ __launch_bounds__(TPB, 2)
void knn_topk_kernel(const float* __restrict__ pos,
                     float* __restrict__ out,
                     int total_n)
{
    extern __shared__ char smraw[];
    float*    sx   = (float*)(smraw + SM_SX);
    float*    sy   = (float*)(smraw + SM_SY);
    float*    sz   = (float*)(smraw + SM_SZ);
    float*    ss   = (float*)(smraw + SM_SS);
    unsigned* pend = (unsigned*)(smraw + SM_PEND);

    const int graph = blockIdx.x / CPG;
    const int base  = graph * NPER;
    const float* gp = pos + (size_t)base * 3;

    // Stage graph points (SoA) + squared norms. ss uses the SAME op order as
    // the dot chain so the self-distance is exactly +0.
    for (int p = threadIdx.x; p < NPER; p += TPB) {
        float x = gp[3 * p + 0];
        float y = gp[3 * p + 1];
        float z = gp[3 * p + 2];
        sx[p] = x; sy[p] = y; sz[p] = z;
        ss[p] = fmaf(z, z, fmaf(y, y, x * x));
    }
    __syncthreads();

    const int   tid = threadIdx.x;
    const int   q   = (blockIdx.x % CPG) * TPB + tid;
    const float qx = sx[q], qy = sy[q], qz = sz[q], qs = ss[q];

    unsigned long long qx2, qy2, qz2, qs2, m2;
    {
        const unsigned xb = __float_as_uint(qx), yb = __float_as_uint(qy);
        const unsigned zb = __float_as_uint(qz), sb = __float_as_uint(qs);
        const unsigned nb = __float_as_uint(-2.0f);
        PACK2(qx2, xb, xb); PACK2(qy2, yb, yb); PACK2(qz2, zb, zb);
        PACK2(qs2, sb, sb); PACK2(m2, nb, nb);
    }

    // Sorted K+1 list (ascending; FIFO order + strict '<' chain => ties keep
    // the earlier/lower index). Self kept, removed at output.
    float bd[KP1];
    int   bi[KP1];
#pragma unroll
    for (int m = 0; m < KP1; ++m) { bd[m] = CUDART_INF_F; bi[m] = -1; }
    float worst = CUDART_INF_F;

    // Absolute FIFO cursor (byte address of next free slot) + bounds.
    const unsigned abase   = (unsigned)__cvta_generic_to_shared(pend + tid);
    unsigned       aaddr   = abase;
    const unsigned athresh = abase + FLUSH_B;

#pragma unroll 1
    for (int j0 = 0; j0 < NPER; j0 += 16) {
        BLOCK8(j0);
        BLOCK8(j0 + 8);
        // One warp-uniform flush vote per 16 candidates.
        if (__any_sync(0xFFFFFFFFu, aaddr >= athresh)) DRAIN();
    }

    DRAIN();

    // Emit: drop the single self entry (idx == q, d == +0), keep first K.
    const int    gq = base + q;
    const size_t Nk = (size_t)total_n * K;
    int w = 0;
#pragma unroll
    for (int m = 0; m < KP1; ++m) {
        if (bi[m] != q && w < K) {
            const size_t e = (size_t)gq * K + w;
            out[e]          = (float)(bi[m] + base);
            out[Nk + e]     = (float)gq;
            out[2 * Nk + e] = bd[m];
            ++w;
        }
    }
}

extern "C" void kernel_launch(void* const* d_in, const int* in_sizes, int n_in,
                              void* d_out, int out_size)
{
    const float* pos = (const float*)d_in[0];
    const int total_n = in_sizes[0] / 3;
    const int ngraphs = total_n / NPER;

    cudaFuncSetAttribute(knn_topk_kernel,
                         cudaFuncAttributeMaxDynamicSharedMemorySize, SM_TOTAL);
    knn_topk_kernel<<<ngraphs * CPG, TPB, SM_TOTAL>>>(pos, (float*)d_out, total_n);
}